// round 1
// baseline (speedup 1.0000x reference)
#include <cuda_runtime.h>
#include <math.h>

#define N_ENTS  100000
#define N_RELS  64
#define EDIM    128
#define KNBR    32
#define BATCH   16384

// ---------------- device-global scratch (no runtime allocation allowed) ----------
__device__ float g_EntN[(size_t)N_ENTS * EDIM];   // maxnorm(ent_table)        51.2 MB
__device__ float g_TrT [(size_t)N_ENTS * EDIM];   // EntN @ Wr^T + Wr_b        51.2 MB
__device__ float g_RelN[(size_t)N_RELS * EDIM];   // maxnorm(rel_table)        32 KB
__device__ float g_X1  [(size_t)BATCH * EDIM];    // h + Nh                    8 MB
__device__ float g_X2  [(size_t)BATCH * EDIM];    // h * Nh                    8 MB

// ---------------- K1: row max-norm for ent_table and rel_table -------------------
// one warp per 128-float row; lane holds one float4
__global__ __launch_bounds__(256) void k_normalize(const float* __restrict__ ent,
                                                   const float* __restrict__ rel) {
    int row = blockIdx.x * 8 + (threadIdx.x >> 5);
    int l   = threadIdx.x & 31;
    const float* src;
    float* dst;
    if (row < N_ENTS) {
        src = ent + (size_t)row * EDIM;
        dst = g_EntN + (size_t)row * EDIM;
    } else {
        int r = row - N_ENTS;
        if (r >= N_RELS) return;
        src = rel + (size_t)r * EDIM;
        dst = g_RelN + (size_t)r * EDIM;
    }
    float4 v = ((const float4*)src)[l];
    float ss = v.x * v.x + v.y * v.y + v.z * v.z + v.w * v.w;
    #pragma unroll
    for (int o = 16; o; o >>= 1) ss += __shfl_xor_sync(0xffffffffu, ss, o);
    float n = sqrtf(ss);
    float s = fminf(1.0f, 1.0f / fmaxf(n, 1e-12f));
    float4 o4 = make_float4(v.x * s, v.y * s, v.z * s, v.w * s);
    ((float4*)dst)[l] = o4;
}

// ---------------- tiled fp32 GEMM: C[M,128] = epi(A[M,128] @ B[128,128]^T + bias) -
// MODE 0: store (acc+bias)                         (TrT precompute)
// MODE 1: store leaky(acc+bias)                    (first bi-interaction term)
// MODE 2: C += leaky(acc+bias)                     (second bi-interaction term)
// 128x128 tile, 256 threads, 8x8 micro-tile per thread. B tile XOR-swizzled.
template <int MODE>
__global__ __launch_bounds__(256) void k_gemm(const float* __restrict__ A,
                                              const float* __restrict__ B,
                                              const float* __restrict__ bias,
                                              float* __restrict__ C, int M) {
    extern __shared__ float sm[];
    float* sA = sm;               // [128][132]  (pad 4 -> 2-way-max LDS conflicts)
    float* sB = sm + 128 * 132;   // [128][128]  xor-swizzled float4 columns

    int tid = threadIdx.x;
    int m0  = blockIdx.x * 128;

    // load A tile (guard rows >= M with zeros)
    #pragma unroll
    for (int i = 0; i < 16; i++) {
        int lin = tid + i * 256;
        int m = lin >> 5, c4 = lin & 31;
        float4 v = make_float4(0.f, 0.f, 0.f, 0.f);
        int gm = m0 + m;
        if (gm < M) v = ((const float4*)A)[(size_t)gm * 32 + c4];
        *(float4*)(sA + m * 132 + c4 * 4) = v;
    }
    // load B tile, xor-swizzle float4 column index by (n>>3)&7
    #pragma unroll
    for (int i = 0; i < 16; i++) {
        int lin = tid + i * 256;
        int n = lin >> 5, c4 = lin & 31;
        float4 v = ((const float4*)B)[n * 32 + c4];
        int c4s = c4 ^ ((n >> 3) & 7);
        *(float4*)(sB + n * 128 + c4s * 4) = v;
    }
    __syncthreads();

    int tx = tid & 15, ty = tid >> 4;
    int mB = ty * 8, nB = tx * 8;

    float acc[8][8];
    #pragma unroll
    for (int i = 0; i < 8; i++)
        #pragma unroll
        for (int j = 0; j < 8; j++) acc[i][j] = 0.f;

    #pragma unroll 4
    for (int kb = 0; kb < 32; kb++) {
        float4 a[8], b[8];
        int kbs = (kb ^ (tx & 7)) * 4;   // (n>>3)&7 == tx&7 for all 8 owned n's
        #pragma unroll
        for (int i = 0; i < 8; i++)
            a[i] = *(const float4*)(sA + (mB + i) * 132 + kb * 4);
        #pragma unroll
        for (int j = 0; j < 8; j++)
            b[j] = *(const float4*)(sB + (nB + j) * 128 + kbs);
        #pragma unroll
        for (int i = 0; i < 8; i++)
            #pragma unroll
            for (int j = 0; j < 8; j++)
                acc[i][j] += a[i].x * b[j].x + a[i].y * b[j].y +
                             a[i].z * b[j].z + a[i].w * b[j].w;
    }

    float bb[8];
    #pragma unroll
    for (int j = 0; j < 8; j++) bb[j] = bias[nB + j];

    #pragma unroll
    for (int i = 0; i < 8; i++) {
        int gm = m0 + mB + i;
        if (gm < M) {
            float r[8];
            #pragma unroll
            for (int j = 0; j < 8; j++) {
                float v = acc[i][j] + bb[j];
                if (MODE >= 1) v = (v > 0.f) ? v : 0.2f * v;
                r[j] = v;
            }
            float4* p = (float4*)(C + (size_t)gm * 128 + nB);
            float4 v0 = make_float4(r[0], r[1], r[2], r[3]);
            float4 v1 = make_float4(r[4], r[5], r[6], r[7]);
            if (MODE == 2) {
                float4 o0 = p[0], o1 = p[1];
                v0.x += o0.x; v0.y += o0.y; v0.z += o0.z; v0.w += o0.w;
                v1.x += o1.x; v1.y += o1.y; v1.z += o1.z; v1.w += o1.w;
            }
            p[0] = v0;
            p[1] = v1;
        }
    }
}

// ---------------- K3: per-batch attention (scores, softmax, Nh) ------------------
// one block (128 threads, 4 warps) per batch element.
// hr_b = TrT[idx_b] (Wr GEMV folded into the precomputed table).
__global__ __launch_bounds__(128) void k_main(const int* __restrict__ idx,
                                              const int* __restrict__ adj_ent,
                                              const int* __restrict__ adj_rel) {
    __shared__ __align__(16) float s_hr[128];
    __shared__ __align__(16) float s_h[128];
    __shared__ float s_sc[32];
    __shared__ float s_att[32];
    __shared__ int   s_eid[32];
    __shared__ int   s_rid[32];

    int b   = blockIdx.x;
    int tid = threadIdx.x;

    int ib = idx[b];
    ib = min(max(ib, 0), N_ENTS - 1);

    if (tid < 32) {
        int e = adj_ent[(size_t)ib * KNBR + tid];
        s_eid[tid] = min(max(e, 0), N_ENTS - 1);
        int r = adj_rel[(size_t)ib * KNBR + tid];
        s_rid[tid] = min(max(r, 0), N_RELS - 1);
    }
    s_hr[tid] = g_TrT[(size_t)ib * EDIM + tid];
    s_h[tid]  = g_EntN[(size_t)ib * EDIM + tid];
    __syncthreads();

    int w = tid >> 5, l = tid & 31;
    float4 hr4 = *(const float4*)(s_hr + l * 4);

    // scores: warp w owns k = w*8 .. w*8+7; lane covers 4 of 128 dims
    #pragma unroll
    for (int kk = 0; kk < 8; kk++) {
        int k = w * 8 + kk;
        int e = s_eid[k], r = s_rid[k];
        float4 tr = *(const float4*)(g_TrT + (size_t)e * EDIM + l * 4);
        float4 rv = *(const float4*)(g_RelN + (size_t)r * EDIM + l * 4);
        float p = tanhf(hr4.x + rv.x) * tr.x + tanhf(hr4.y + rv.y) * tr.y +
                  tanhf(hr4.z + rv.z) * tr.z + tanhf(hr4.w + rv.w) * tr.w;
        #pragma unroll
        for (int o = 16; o; o >>= 1) p += __shfl_xor_sync(0xffffffffu, p, o);
        if (l == 0) s_sc[k] = p;
    }
    __syncthreads();

    // softmax over K=32 (warp 0), numerically stable (matches jax.nn.softmax)
    if (tid < 32) {
        float sc = s_sc[tid];
        float mx = sc;
        #pragma unroll
        for (int o = 16; o; o >>= 1) mx = fmaxf(mx, __shfl_xor_sync(0xffffffffu, mx, o));
        float ex = __expf(sc - mx);
        float sum = ex;
        #pragma unroll
        for (int o = 16; o; o >>= 1) sum += __shfl_xor_sync(0xffffffffu, sum, o);
        s_att[tid] = ex / sum;
    }
    __syncthreads();

    // Nh[d] = sum_k att[k] * EntN[eid_k][d] ; thread d, coalesced row segments
    float acc = 0.f;
    #pragma unroll
    for (int k = 0; k < KNBR; k++)
        acc = fmaf(s_att[k], g_EntN[(size_t)s_eid[k] * EDIM + tid], acc);

    float hv = s_h[tid];
    g_X1[(size_t)b * EDIM + tid] = hv + acc;
    g_X2[(size_t)b * EDIM + tid] = hv * acc;
}

// ---------------- launch ---------------------------------------------------------
extern "C" void kernel_launch(void* const* d_in, const int* in_sizes, int n_in,
                              void* d_out, int out_size) {
    const int*   idx     = (const int*)d_in[0];
    const int*   adj_ent = (const int*)d_in[1];
    const int*   adj_rel = (const int*)d_in[2];
    const float* ent     = (const float*)d_in[3];
    const float* rel     = (const float*)d_in[4];
    const float* Wr_w    = (const float*)d_in[5];
    const float* Wr_b    = (const float*)d_in[6];
    const float* W1_w    = (const float*)d_in[7];
    const float* W1_b    = (const float*)d_in[8];
    const float* W2_w    = (const float*)d_in[9];
    const float* W2_b    = (const float*)d_in[10];
    float* out = (float*)d_out;

    const size_t SMEM = (size_t)(128 * 132 + 128 * 128) * sizeof(float); // 133120 B
    cudaFuncSetAttribute(k_gemm<0>, cudaFuncAttributeMaxDynamicSharedMemorySize, (int)SMEM);
    cudaFuncSetAttribute(k_gemm<1>, cudaFuncAttributeMaxDynamicSharedMemorySize, (int)SMEM);
    cudaFuncSetAttribute(k_gemm<2>, cudaFuncAttributeMaxDynamicSharedMemorySize, (int)SMEM);

    float *EntN, *TrT, *X1, *X2;
    cudaGetSymbolAddress((void**)&EntN, g_EntN);
    cudaGetSymbolAddress((void**)&TrT,  g_TrT);
    cudaGetSymbolAddress((void**)&X1,   g_X1);
    cudaGetSymbolAddress((void**)&X2,   g_X2);

    // K1: maxnorm tables
    k_normalize<<<(N_ENTS + N_RELS + 7) / 8, 256>>>(ent, rel);
    // K2: TrT = EntN @ Wr^T + Wr_b   (also serves as hr lookup table)
    k_gemm<0><<<(N_ENTS + 127) / 128, 256, SMEM>>>(EntN, Wr_w, Wr_b, TrT, N_ENTS);
    // K3: attention + aggregation -> X1 = h+Nh, X2 = h*Nh
    k_main<<<BATCH, 128>>>(idx, adj_ent, adj_rel);
    // K4: out = leaky(X1@W1^T+b1) + leaky(X2@W2^T+b2)
    k_gemm<1><<<BATCH / 128, 256, SMEM>>>(X1, W1_w, W1_b, out, BATCH);
    k_gemm<2><<<BATCH / 128, 256, SMEM>>>(X2, W2_w, W2_b, out, BATCH);
}

// round 3
// speedup vs baseline: 1.4218x; 1.4218x over previous
#include <cuda_runtime.h>
#include <cuda_bf16.h>
#include <math.h>
#include <stdint.h>

#define N_ENTS  100000
#define N_RELS  64
#define EDIM    128
#define KNBR    32
#define BATCH   16384

// ---------------- device-global scratch ------------------------------------------
__device__ float g_EntN[(size_t)N_ENTS * EDIM];
__device__ float g_TrT [(size_t)N_ENTS * EDIM];
__device__ float g_RelN[(size_t)N_RELS * EDIM];
__device__ float g_X1  [(size_t)BATCH * EDIM];
__device__ float g_X2  [(size_t)BATCH * EDIM];

// ---------------- helpers ----------------------------------------------------------
__device__ __forceinline__ uint32_t smem_u32(const void* p) {
    uint32_t a;
    asm("{ .reg .u64 t; cvta.to.shared.u64 t, %1; cvt.u32.u64 %0, t; }" : "=r"(a) : "l"(p));
    return a;
}
__device__ __forceinline__ void ldmx4(uint32_t& r0, uint32_t& r1, uint32_t& r2, uint32_t& r3,
                                      uint32_t addr) {
    asm volatile("ldmatrix.sync.aligned.m8n8.x4.shared.b16 {%0,%1,%2,%3}, [%4];"
                 : "=r"(r0), "=r"(r1), "=r"(r2), "=r"(r3) : "r"(addr));
}
__device__ __forceinline__ void mma_bf16(float* d, const uint32_t* a, const uint32_t* b) {
    asm volatile(
        "mma.sync.aligned.m16n8k16.row.col.f32.bf16.bf16.f32 "
        "{%0,%1,%2,%3}, {%4,%5,%6,%7}, {%8,%9}, {%0,%1,%2,%3};"
        : "+f"(d[0]), "+f"(d[1]), "+f"(d[2]), "+f"(d[3])
        : "r"(a[0]), "r"(a[1]), "r"(a[2]), "r"(a[3]), "r"(b[0]), "r"(b[1]));
}
__device__ __forceinline__ uint32_t pk_bf2(__nv_bfloat16 a, __nv_bfloat16 b) {
    __nv_bfloat162 t(a, b);
    return *(uint32_t*)&t;
}

// padded bf16 tile: 128 rows x 136 cols (272B row stride -> conflict-free ldmatrix)
#define LDT 136
#define TILE_B (128 * LDT * 2)
#define OFF_BIAS 0
#define OFF_AH   512
#define OFF_AL   (512 + TILE_B)
#define OFF_BH   (512 + 2 * TILE_B)
#define OFF_BL   (512 + 3 * TILE_B)
#define SMEM_MM  (512 + 4 * TILE_B)      // 139,776 B

// load 128x128 fp32 tile (rows >= rows_valid zeroed), split bf16 hi/lo into smem
__device__ __forceinline__ void load_split(const float* __restrict__ src, int rows_valid,
                                           char* sm, int off_h, int off_l, int tid) {
    #pragma unroll
    for (int i = 0; i < 8; i++) {
        int g = tid + i * 256;
        int row = g >> 4, c8 = g & 15, col0 = c8 * 8;
        float4 v0 = make_float4(0.f, 0.f, 0.f, 0.f), v1 = v0;
        if (row < rows_valid) {
            const float4* p = (const float4*)src + (size_t)row * 32 + c8 * 2;
            v0 = p[0];
            v1 = p[1];
        }
        float f[8] = {v0.x, v0.y, v0.z, v0.w, v1.x, v1.y, v1.z, v1.w};
        __nv_bfloat16 h[8], l[8];
        #pragma unroll
        for (int j = 0; j < 8; j++) {
            h[j] = __float2bfloat16(f[j]);
            l[j] = __float2bfloat16(f[j] - __bfloat162float(h[j]));
        }
        uint4 hv = make_uint4(pk_bf2(h[0], h[1]), pk_bf2(h[2], h[3]),
                              pk_bf2(h[4], h[5]), pk_bf2(h[6], h[7]));
        uint4 lv = make_uint4(pk_bf2(l[0], l[1]), pk_bf2(l[2], l[3]),
                              pk_bf2(l[4], l[5]), pk_bf2(l[6], l[7]));
        size_t o = (size_t)row * LDT * 2 + col0 * 2;
        *(uint4*)(sm + off_h + o) = hv;
        *(uint4*)(sm + off_l + o) = lv;
    }
}

// ---------------- mma.sync GEMM: C[M,128] = epi(A[M,128] @ B[128,128]^T + bias) ----
// MODE 0: store; MODE 1: store leaky; MODE 2: += leaky
// 256 threads, CTA tile 128x128, warp tile 64x32, bf16 hi/lo 3-pass into fp32 acc.
template <int MODE>
__global__ __launch_bounds__(256, 1) void k_gemm_mma(const float* __restrict__ A,
                                                     const float* __restrict__ B,
                                                     const float* __restrict__ bias,
                                                     float* __restrict__ C, int M) {
    extern __shared__ char sm[];
    uint32_t smb = smem_u32(sm);
    int tid  = threadIdx.x;
    int wid  = tid >> 5, lane = tid & 31;
    int wy   = wid >> 2, wx = wid & 3;          // 2 x 4 warp grid
    int m0   = blockIdx.x * 128;

    if (tid < 128) ((float*)(sm + OFF_BIAS))[tid] = bias[tid];
    load_split(A + (size_t)m0 * EDIM, M - m0, sm, OFF_AH, OFF_AL, tid);
    load_split(B, 128, sm, OFF_BH, OFF_BL, tid);
    __syncthreads();

    // per-lane ldmatrix base offsets
    int rowA  = wy * 64 + (lane & 15);          // + mi*16
    int colA  = (lane >> 4) * 8;                // + k0
    int nrow  = wx * 32 + (lane & 7) + ((lane >> 4) ? 8 : 0);   // + nj2*16
    int kaddB = ((lane >> 3) & 1) * 8;          // + k0

    uint32_t aBaseH = smb + OFF_AH, aBaseL = smb + OFF_AL;
    uint32_t bBaseH = smb + OFF_BH, bBaseL = smb + OFF_BL;

    float d[4][4][4];
    #pragma unroll
    for (int i = 0; i < 4; i++)
        #pragma unroll
        for (int j = 0; j < 4; j++)
            #pragma unroll
            for (int q = 0; q < 4; q++) d[i][j][q] = 0.f;

    #pragma unroll
    for (int ks = 0; ks < 8; ks++) {
        int k0 = ks * 16;
        #pragma unroll
        for (int pass = 0; pass < 3; pass++) {
            uint32_t aB = (pass == 2) ? aBaseL : aBaseH;
            uint32_t bB = (pass == 1) ? bBaseL : bBaseH;

            uint32_t a[4][4];
            #pragma unroll
            for (int mi = 0; mi < 4; mi++) {
                uint32_t addr = aB + (uint32_t)(((rowA + mi * 16) * LDT + k0 + colA) * 2);
                ldmx4(a[mi][0], a[mi][1], a[mi][2], a[mi][3], addr);
            }
            uint32_t b[4][2];
            #pragma unroll
            for (int nj2 = 0; nj2 < 2; nj2++) {
                uint32_t addr = bB + (uint32_t)(((nrow + nj2 * 16) * LDT + k0 + kaddB) * 2);
                uint32_t r0, r1, r2, r3;
                ldmx4(r0, r1, r2, r3, addr);
                b[nj2 * 2 + 0][0] = r0; b[nj2 * 2 + 0][1] = r1;
                b[nj2 * 2 + 1][0] = r2; b[nj2 * 2 + 1][1] = r3;
            }
            #pragma unroll
            for (int mi = 0; mi < 4; mi++)
                #pragma unroll
                for (int nj = 0; nj < 4; nj++)
                    mma_bf16(d[mi][nj], a[mi], b[nj]);
        }
    }

    // epilogue
    const float* sb = (const float*)(sm + OFF_BIAS);
    int qrow = lane >> 2, qcol = (lane & 3) * 2;
    #pragma unroll
    for (int mi = 0; mi < 4; mi++) {
        #pragma unroll
        for (int half = 0; half < 2; half++) {
            int gm = m0 + wy * 64 + mi * 16 + qrow + half * 8;
            if (gm < M) {
                #pragma unroll
                for (int nj = 0; nj < 4; nj++) {
                    int gc = wx * 32 + nj * 8 + qcol;
                    float x0 = d[mi][nj][half * 2 + 0] + sb[gc];
                    float x1 = d[mi][nj][half * 2 + 1] + sb[gc + 1];
                    if (MODE >= 1) {
                        x0 = (x0 > 0.f) ? x0 : 0.2f * x0;
                        x1 = (x1 > 0.f) ? x1 : 0.2f * x1;
                    }
                    float2* p = (float2*)(C + (size_t)gm * 128 + gc);
                    if (MODE == 2) {
                        float2 c = *p;
                        x0 += c.x;
                        x1 += c.y;
                    }
                    *p = make_float2(x0, x1);
                }
            }
        }
    }
}

// ---------------- K1: row max-norm -------------------------------------------------
__global__ __launch_bounds__(256) void k_normalize(const float* __restrict__ ent,
                                                   const float* __restrict__ rel) {
    int row = blockIdx.x * 8 + (threadIdx.x >> 5);
    int l   = threadIdx.x & 31;
    const float* src;
    float* dst;
    if (row < N_ENTS) {
        src = ent + (size_t)row * EDIM;
        dst = g_EntN + (size_t)row * EDIM;
    } else {
        int r = row - N_ENTS;
        if (r >= N_RELS) return;
        src = rel + (size_t)r * EDIM;
        dst = g_RelN + (size_t)r * EDIM;
    }
    float4 v = ((const float4*)src)[l];
    float ss = v.x * v.x + v.y * v.y + v.z * v.z + v.w * v.w;
    #pragma unroll
    for (int o = 16; o; o >>= 1) ss += __shfl_xor_sync(0xffffffffu, ss, o);
    float n = sqrtf(ss);
    float s = fminf(1.0f, 1.0f / fmaxf(n, 1e-12f));
    ((float4*)dst)[l] = make_float4(v.x * s, v.y * s, v.z * s, v.w * s);
}

// ---------------- K3: attention + aggregation --------------------------------------
__global__ __launch_bounds__(128) void k_main(const int* __restrict__ idx,
                                              const int* __restrict__ adj_ent,
                                              const int* __restrict__ adj_rel) {
    __shared__ __align__(16) float s_hr[128];
    __shared__ __align__(16) float s_h[128];
    __shared__ float s_sc[32];
    __shared__ float s_att[32];
    __shared__ int   s_eid[32];
    __shared__ int   s_rid[32];

    int b   = blockIdx.x;
    int tid = threadIdx.x;

    int ib = idx[b];
    ib = min(max(ib, 0), N_ENTS - 1);

    if (tid < 32) {
        int e = adj_ent[(size_t)ib * KNBR + tid];
        s_eid[tid] = min(max(e, 0), N_ENTS - 1);
        int r = adj_rel[(size_t)ib * KNBR + tid];
        s_rid[tid] = min(max(r, 0), N_RELS - 1);
    }
    s_hr[tid] = g_TrT[(size_t)ib * EDIM + tid];
    s_h[tid]  = g_EntN[(size_t)ib * EDIM + tid];
    __syncthreads();

    int w = tid >> 5, l = tid & 31;
    float4 hr4 = *(const float4*)(s_hr + l * 4);

    #pragma unroll
    for (int kk = 0; kk < 8; kk++) {
        int k = w * 8 + kk;
        int e = s_eid[k], r = s_rid[k];
        float4 tr = *(const float4*)(g_TrT + (size_t)e * EDIM + l * 4);
        float4 rv = *(const float4*)(g_RelN + (size_t)r * EDIM + l * 4);
        float p = tanhf(hr4.x + rv.x) * tr.x + tanhf(hr4.y + rv.y) * tr.y +
                  tanhf(hr4.z + rv.z) * tr.z + tanhf(hr4.w + rv.w) * tr.w;
        #pragma unroll
        for (int o = 16; o; o >>= 1) p += __shfl_xor_sync(0xffffffffu, p, o);
        if (l == 0) s_sc[k] = p;
    }
    __syncthreads();

    if (tid < 32) {
        float sc = s_sc[tid];
        float mx = sc;
        #pragma unroll
        for (int o = 16; o; o >>= 1) mx = fmaxf(mx, __shfl_xor_sync(0xffffffffu, mx, o));
        float ex = __expf(sc - mx);
        float sum = ex;
        #pragma unroll
        for (int o = 16; o; o >>= 1) sum += __shfl_xor_sync(0xffffffffu, sum, o);
        s_att[tid] = ex / sum;
    }
    __syncthreads();

    float acc = 0.f;
    #pragma unroll
    for (int k = 0; k < KNBR; k++)
        acc = fmaf(s_att[k], g_EntN[(size_t)s_eid[k] * EDIM + tid], acc);

    float hv = s_h[tid];
    g_X1[(size_t)b * EDIM + tid] = hv + acc;
    g_X2[(size_t)b * EDIM + tid] = hv * acc;
}

// ---------------- launch ------------------------------------------------------------
extern "C" void kernel_launch(void* const* d_in, const int* in_sizes, int n_in,
                              void* d_out, int out_size) {
    const int*   idx     = (const int*)d_in[0];
    const int*   adj_ent = (const int*)d_in[1];
    const int*   adj_rel = (const int*)d_in[2];
    const float* ent     = (const float*)d_in[3];
    const float* rel     = (const float*)d_in[4];
    const float* Wr_w    = (const float*)d_in[5];
    const float* Wr_b    = (const float*)d_in[6];
    const float* W1_w    = (const float*)d_in[7];
    const float* W1_b    = (const float*)d_in[8];
    const float* W2_w    = (const float*)d_in[9];
    const float* W2_b    = (const float*)d_in[10];
    float* out = (float*)d_out;

    cudaFuncSetAttribute(k_gemm_mma<0>, cudaFuncAttributeMaxDynamicSharedMemorySize, SMEM_MM);
    cudaFuncSetAttribute(k_gemm_mma<1>, cudaFuncAttributeMaxDynamicSharedMemorySize, SMEM_MM);
    cudaFuncSetAttribute(k_gemm_mma<2>, cudaFuncAttributeMaxDynamicSharedMemorySize, SMEM_MM);

    float *EntN, *TrT, *X1, *X2;
    cudaGetSymbolAddress((void**)&EntN, g_EntN);
    cudaGetSymbolAddress((void**)&TrT,  g_TrT);
    cudaGetSymbolAddress((void**)&X1,   g_X1);
    cudaGetSymbolAddress((void**)&X2,   g_X2);

    k_normalize<<<(N_ENTS + N_RELS + 7) / 8, 256>>>(ent, rel);
    k_gemm_mma<0><<<(N_ENTS + 127) / 128, 256, SMEM_MM>>>(EntN, Wr_w, Wr_b, TrT, N_ENTS);
    k_main<<<BATCH, 128>>>(idx, adj_ent, adj_rel);
    k_gemm_mma<1><<<BATCH / 128, 256, SMEM_MM>>>(X1, W1_w, W1_b, out, BATCH);
    k_gemm_mma<2><<<BATCH / 128, 256, SMEM_MM>>>(X2, W2_w, W2_b, out, BATCH);
}